// round 9
// baseline (speedup 1.0000x reference)
#include <cuda_runtime.h>
#include <cuda_bf16.h>
#include <math.h>
#include <cstdint>

#define B_  4
#define S_  2048
#define D_  1024
#define H_  16
#define DK_ 64
#define MTOT (B_*S_)   // 8192
#define NX_  (MTOT * D_)      // 8388608
#define NW_  (D_ * D_)        // 1048576

typedef __nv_bfloat16 bf16;

__device__ bf16 g_Ah[(size_t)NX_];
__device__ bf16 g_Al[(size_t)NX_];
__device__ bf16 g_Wh[4 * (size_t)NW_];
__device__ bf16 g_Wl[4 * (size_t)NW_];
__device__ bf16 g_Qh[(size_t)NX_];
__device__ bf16 g_Ql[(size_t)NX_];
__device__ bf16 g_Kh[(size_t)NX_];
__device__ bf16 g_Kl[(size_t)NX_];
__device__ bf16 g_Vh[(size_t)NX_];
__device__ bf16 g_Vl[(size_t)NX_];

__device__ __forceinline__ uint32_t smem_to_u32(const void* p) {
    uint32_t a;
    asm("{ .reg .u64 t; cvta.to.shared.u64 t, %1; cvt.u32.u64 %0, t; }" : "=r"(a) : "l"(p));
    return a;
}
__device__ __forceinline__ void ldsm4(uint32_t* r, uint32_t addr) {
    asm volatile("ldmatrix.sync.aligned.m8n8.x4.shared.b16 {%0,%1,%2,%3}, [%4];"
                 : "=r"(r[0]), "=r"(r[1]), "=r"(r[2]), "=r"(r[3]) : "r"(addr));
}
__device__ __forceinline__ void ldsm4t(uint32_t* r, uint32_t addr) {
    asm volatile("ldmatrix.sync.aligned.m8n8.x4.trans.shared.b16 {%0,%1,%2,%3}, [%4];"
                 : "=r"(r[0]), "=r"(r[1]), "=r"(r[2]), "=r"(r[3]) : "r"(addr));
}
__device__ __forceinline__ void mma_bf16(float* d, const uint32_t* a, const uint32_t* b) {
    asm volatile("mma.sync.aligned.m16n8k16.row.col.f32.bf16.bf16.f32 "
                 "{%0,%1,%2,%3}, {%4,%5,%6,%7}, {%8,%9}, {%0,%1,%2,%3};"
                 : "+f"(d[0]), "+f"(d[1]), "+f"(d[2]), "+f"(d[3])
                 : "r"(a[0]), "r"(a[1]), "r"(a[2]), "r"(a[3]), "r"(b[0]), "r"(b[1]));
}
#define CP_ASYNC16(s, g) \
    asm volatile("cp.async.cg.shared.global [%0], [%1], 16;" :: "r"(s), "l"(g))
#define CP_COMMIT()  asm volatile("cp.async.commit_group;" ::: "memory")
#define CP_WAIT0()   asm volatile("cp.async.wait_group 0;" ::: "memory")
#define CP_WAIT1()   asm volatile("cp.async.wait_group 1;" ::: "memory")

__device__ __forceinline__ uint32_t pack_bf16(float a, float b) {
    __nv_bfloat162 t = __floats2bfloat162_rn(a, b);
    return *(uint32_t*)&t;
}

// ---------------------------------------------------------------------------
__global__ void cvt_all(const float* __restrict__ X,  const float* __restrict__ Wq,
                        const float* __restrict__ Wk, const float* __restrict__ Wv,
                        const float* __restrict__ Wo,
                        bf16* __restrict__ Ah, bf16* __restrict__ Al,
                        bf16* __restrict__ Wh, bf16* __restrict__ Wl)
{
    size_t i = (size_t)blockIdx.x * 256 + threadIdx.x;
    const float* src; bf16 *h, *l; size_t off;
    if (i < (size_t)NX_) {
        src = X; h = Ah; l = Al; off = i;
    } else {
        size_t j = i - NX_;
        int w = (int)(j >> 20);
        off = j & (NW_ - 1);
        src = (w == 0) ? Wq : (w == 1) ? Wk : (w == 2) ? Wv : Wo;
        h = Wh + (size_t)w * NW_;
        l = Wl + (size_t)w * NW_;
    }
    float v = src[off];
    bf16 hh = __float2bfloat16(v);
    h[off] = hh;
    l[off] = __float2bfloat16(v - __bfloat162float(hh));
}

// ---------------------------------------------------------------------------
// bf16x3 GEMM, mma.sync. MMA passes batched (hh x8, hl x8, lh x8) to keep
// same-accumulator reuse distance = 8 MMAs (HMMA latency hiding).
// ---------------------------------------------------------------------------
#define KC        32
#define TSTRIDE   40
#define TILE_B    (128 * TSTRIDE * 2)
#define STAGE_B   (4 * TILE_B)
#define NSTAGE    3
#define GEMM_SMEM (NSTAGE * STAGE_B)        // 122880

__global__ __launch_bounds__(512, 1)
void gemm_tc_kernel(const bf16* __restrict__ Ah, const bf16* __restrict__ Al,
                    const bf16* __restrict__ B0h, const bf16* __restrict__ B0l,
                    const bf16* __restrict__ B1h, const bf16* __restrict__ B1l,
                    const bf16* __restrict__ B2h, const bf16* __restrict__ B2l,
                    bf16* __restrict__ Yh0, bf16* __restrict__ Yl0,
                    bf16* __restrict__ Yh1, bf16* __restrict__ Yl1,
                    bf16* __restrict__ Yh2, bf16* __restrict__ Yl2,
                    float* __restrict__ Yf, float sc0)
{
    const bf16* Bh = (blockIdx.z == 0) ? B0h : (blockIdx.z == 1) ? B1h : B2h;
    const bf16* Bl = (blockIdx.z == 0) ? B0l : (blockIdx.z == 1) ? B1l : B2l;
    bf16* Yh = (blockIdx.z == 0) ? Yh0 : (blockIdx.z == 1) ? Yh1 : Yh2;
    bf16* Yl = (blockIdx.z == 0) ? Yl0 : (blockIdx.z == 1) ? Yl1 : Yl2;
    const float osc = (blockIdx.z == 0) ? sc0 : 1.f;

    extern __shared__ char smem[];
    const uint32_t sb = smem_to_u32(smem);
    const int tid = threadIdx.x;
    const int wid = tid >> 5;
    const int lid = tid & 31;
    const int wm  = wid >> 2;
    const int wn  = wid & 3;
    const int m0  = blockIdx.y * 128;
    const int n0  = blockIdx.x * 128;

    const int grow = tid >> 2;
    const uint32_t s_off = (uint32_t)grow * (TSTRIDE * 2) + (uint32_t)(tid & 3) * 16;
    const size_t gA = (size_t)(m0 + grow) * 1024 + (tid & 3) * 8;
    const size_t gB = (size_t)(n0 + grow) * 1024 + (tid & 3) * 8;

    const uint32_t aRow = (uint32_t)(wm * 32 + (lid & 15)) * (TSTRIDE * 2) + ((lid & 16) ? 16u : 0u);
    const uint32_t bRow = (uint32_t)(wn * 32 + (lid & 7) + ((lid & 16) ? 8 : 0)) * (TSTRIDE * 2)
                          + ((lid & 8) ? 16u : 0u);

    float acc[2][4][4];
#pragma unroll
    for (int mb = 0; mb < 2; mb++)
#pragma unroll
        for (int nb = 0; nb < 4; nb++)
#pragma unroll
            for (int q = 0; q < 4; q++) acc[mb][nb][q] = 0.f;

    auto issue = [&](int stage, int c) {
        const uint32_t st = sb + (uint32_t)stage * STAGE_B + s_off;
        const size_t ko = (size_t)c * KC;
        CP_ASYNC16(st + 0 * TILE_B, Ah + gA + ko);
        CP_ASYNC16(st + 1 * TILE_B, Al + gA + ko);
        CP_ASYNC16(st + 2 * TILE_B, Bh + gB + ko);
        CP_ASYNC16(st + 3 * TILE_B, Bl + gB + ko);
    };

    issue(0, 0); CP_COMMIT();
    issue(1, 1); CP_COMMIT();

    int stage = 0, nstage = 2;
    for (int c = 0; c < 32; c++) {
        if (c < 30) CP_WAIT1(); else CP_WAIT0();
        __syncthreads();
        if (c + 2 < 32) {
            issue(nstage, c + 2); CP_COMMIT();
            if (++nstage == NSTAGE) nstage = 0;
        }

        const uint32_t st = sb + (uint32_t)stage * STAGE_B;
#pragma unroll
        for (int ks = 0; ks < 2; ks++) {
            const uint32_t kb = (uint32_t)ks * 32;
            uint32_t fa[2][4], fal[2][4], fb_h[2][4], fb_l[2][4];
            // all fragments up-front so LDSM overlaps the MMA streams
#pragma unroll
            for (int mb = 0; mb < 2; mb++) {
                ldsm4(fa[mb],  st + 0 * TILE_B + aRow + (uint32_t)mb * (16 * TSTRIDE * 2) + kb);
                ldsm4(fal[mb], st + 1 * TILE_B + aRow + (uint32_t)mb * (16 * TSTRIDE * 2) + kb);
            }
#pragma unroll
            for (int nb = 0; nb < 2; nb++) {
                ldsm4(fb_h[nb], st + 2 * TILE_B + bRow + (uint32_t)nb * (16 * TSTRIDE * 2) + kb);
                ldsm4(fb_l[nb], st + 3 * TILE_B + bRow + (uint32_t)nb * (16 * TSTRIDE * 2) + kb);
            }
            // pass 1: hi*hi  (8 independent accumulators)
#pragma unroll
            for (int mb = 0; mb < 2; mb++)
#pragma unroll
                for (int nb = 0; nb < 4; nb++)
                    mma_bf16(acc[mb][nb], fa[mb], &fb_h[nb >> 1][(nb & 1) * 2]);
            // pass 2: hi*lo
#pragma unroll
            for (int mb = 0; mb < 2; mb++)
#pragma unroll
                for (int nb = 0; nb < 4; nb++)
                    mma_bf16(acc[mb][nb], fa[mb], &fb_l[nb >> 1][(nb & 1) * 2]);
            // pass 3: lo*hi
#pragma unroll
            for (int mb = 0; mb < 2; mb++)
#pragma unroll
                for (int nb = 0; nb < 4; nb++)
                    mma_bf16(acc[mb][nb], fal[mb], &fb_h[nb >> 1][(nb & 1) * 2]);
        }
        if (++stage == NSTAGE) stage = 0;
    }

    const int rr = lid >> 2;
    const int cc = (lid & 3) * 2;
    if (Yf) {
#pragma unroll
        for (int mb = 0; mb < 2; mb++) {
            const int row = m0 + wm * 32 + mb * 16 + rr;
#pragma unroll
            for (int nb = 0; nb < 4; nb++) {
                const int col = n0 + wn * 32 + nb * 8 + cc;
                *(float2*)&Yf[(size_t)row * 1024 + col]       = make_float2(acc[mb][nb][0], acc[mb][nb][1]);
                *(float2*)&Yf[(size_t)(row + 8) * 1024 + col] = make_float2(acc[mb][nb][2], acc[mb][nb][3]);
            }
        }
    } else {
#pragma unroll
        for (int mb = 0; mb < 2; mb++) {
            const int row = m0 + wm * 32 + mb * 16 + rr;
#pragma unroll
            for (int nb = 0; nb < 4; nb++) {
                const int col = n0 + wn * 32 + nb * 8 + cc;
#pragma unroll
                for (int half = 0; half < 2; half++) {
                    float v0 = acc[mb][nb][half * 2 + 0] * osc;
                    float v1 = acc[mb][nb][half * 2 + 1] * osc;
                    bf16 h0 = __float2bfloat16(v0), h1 = __float2bfloat16(v1);
                    float l0 = v0 - __bfloat162float(h0), l1 = v1 - __bfloat162float(h1);
                    size_t off = (size_t)(row + half * 8) * 1024 + col;
                    *(uint32_t*)&Yh[off] = pack_bf16(__bfloat162float(h0), __bfloat162float(h1));
                    *(uint32_t*)&Yl[off] = pack_bf16(l0, l1);
                }
            }
        }
    }
}

// ---------------------------------------------------------------------------
// Flash attention, mma.sync bf16x3. QK^T passes batched per-nt sweeps
// (same-acc reuse distance 8). PV unchanged (distance 2).
// ---------------------------------------------------------------------------
#define AT_STR   144
#define AT_TILE  (64 * AT_STR)
#define AT_STAGE (4 * AT_TILE)
#define AT_QOFF  (2 * AT_STAGE)
#define AT_SMEM  (AT_QOFF + 2 * 128 * AT_STR)   // 110592

__global__ __launch_bounds__(256)
void attn_tc_kernel(const bf16* __restrict__ Qh, const bf16* __restrict__ Ql,
                    const bf16* __restrict__ Kh, const bf16* __restrict__ Kl,
                    const bf16* __restrict__ Vh, const bf16* __restrict__ Vl,
                    bf16* __restrict__ Ch, bf16* __restrict__ Cl)
{
    extern __shared__ char smem[];
    const uint32_t sb = smem_to_u32(smem);
    const int tid = threadIdx.x;
    const int wid = tid >> 5;
    const int lid = tid & 31;
    const int q0  = blockIdx.x * 128;
    const int h   = blockIdx.y;
    const int b   = blockIdx.z;
    const size_t ebase = ((size_t)b * S_) * D_ + (size_t)h * DK_;

    {
#pragma unroll
        for (int l = 0; l < 4; l++) {
            int idx = tid + l * 256;
            int row = idx >> 3, c8 = idx & 7;
            size_t g = ebase + (size_t)(q0 + row) * 1024 + c8 * 8;
            uint32_t s = sb + AT_QOFF + (uint32_t)row * AT_STR + c8 * 16;
            CP_ASYNC16(s, Qh + g);
            CP_ASYNC16(s + 128 * AT_STR, Ql + g);
        }
#pragma unroll
        for (int l = 0; l < 2; l++) {
            int idx = tid + l * 256;
            int row = idx >> 3, c8 = idx & 7;
            size_t g = ebase + (size_t)row * 1024 + c8 * 8;
            uint32_t s = sb + (uint32_t)row * AT_STR + c8 * 16;
            CP_ASYNC16(s + 0 * AT_TILE, Kh + g);
            CP_ASYNC16(s + 1 * AT_TILE, Kl + g);
            CP_ASYNC16(s + 2 * AT_TILE, Vh + g);
            CP_ASYNC16(s + 3 * AT_TILE, Vl + g);
        }
        CP_COMMIT();
        CP_WAIT0();
        __syncthreads();
    }

    const uint32_t qAddrBase = sb + AT_QOFF + (uint32_t)(wid * 16 + (lid & 15)) * AT_STR
                               + ((lid & 16) ? 16u : 0u);
    uint32_t qh[4][4];
#pragma unroll
    for (int ks = 0; ks < 4; ks++) ldsm4(qh[ks], qAddrBase + ks * 32);

    float m0 = -INFINITY, m1 = -INFINITY, l0 = 0.f, l1 = 0.f;
    float o[8][4];
#pragma unroll
    for (int dt = 0; dt < 8; dt++)
#pragma unroll
        for (int q = 0; q < 4; q++) o[dt][q] = 0.f;

    const uint32_t kRow = (uint32_t)((lid & 7) + ((lid & 16) ? 8 : 0)) * AT_STR + ((lid & 8) ? 16u : 0u);
    const uint32_t vRow = (uint32_t)(lid & 15) * AT_STR + ((lid & 16) ? 16u : 0u);

    for (int c = 0; c < 32; c++) {
        const uint32_t st = sb + (uint32_t)(c & 1) * AT_STAGE;

        if (c + 1 < 32) {
            const uint32_t sn = sb + (uint32_t)((c + 1) & 1) * AT_STAGE;
            const int ks0 = (c + 1) * 64;
#pragma unroll
            for (int l = 0; l < 2; l++) {
                int idx = tid + l * 256;
                int row = idx >> 3, c8 = idx & 7;
                size_t g = ebase + (size_t)(ks0 + row) * 1024 + c8 * 8;
                uint32_t s = sn + (uint32_t)row * AT_STR + c8 * 16;
                CP_ASYNC16(s + 0 * AT_TILE, Kh + g);
                CP_ASYNC16(s + 1 * AT_TILE, Kl + g);
                CP_ASYNC16(s + 2 * AT_TILE, Vh + g);
                CP_ASYNC16(s + 3 * AT_TILE, Vl + g);
            }
            CP_COMMIT();
        }

        float s4[8][4];
#pragma unroll
        for (int nt = 0; nt < 8; nt++)
#pragma unroll
            for (int q = 0; q < 4; q++) s4[nt][q] = 0.f;

#pragma unroll
        for (int ks = 0; ks < 4; ks++) {
            uint32_t bh[4][4], bl[4][4], qlr[4];
#pragma unroll
            for (int g = 0; g < 4; g++) {
                uint32_t a = st + (uint32_t)(16 * g) * AT_STR + kRow + ks * 32;
                ldsm4(bh[g], a);
                ldsm4(bl[g], a + AT_TILE);
            }
            ldsm4(qlr, qAddrBase + 128 * AT_STR + ks * 32);
            // batched passes: same-acc reuse distance = 8 MMAs
#pragma unroll
            for (int nt = 0; nt < 8; nt++)
                mma_bf16(s4[nt], qh[ks], &bh[nt >> 1][(nt & 1) * 2]);
#pragma unroll
            for (int nt = 0; nt < 8; nt++)
                mma_bf16(s4[nt], qh[ks], &bl[nt >> 1][(nt & 1) * 2]);
#pragma unroll
            for (int nt = 0; nt < 8; nt++)
                mma_bf16(s4[nt], qlr,    &bh[nt >> 1][(nt & 1) * 2]);
        }

        float mx0 = -INFINITY, mx1 = -INFINITY;
#pragma unroll
        for (int nt = 0; nt < 8; nt++) {
            mx0 = fmaxf(mx0, fmaxf(s4[nt][0], s4[nt][1]));
            mx1 = fmaxf(mx1, fmaxf(s4[nt][2], s4[nt][3]));
        }
        mx0 = fmaxf(mx0, __shfl_xor_sync(0xffffffffu, mx0, 1));
        mx0 = fmaxf(mx0, __shfl_xor_sync(0xffffffffu, mx0, 2));
        mx1 = fmaxf(mx1, __shfl_xor_sync(0xffffffffu, mx1, 1));
        mx1 = fmaxf(mx1, __shfl_xor_sync(0xffffffffu, mx1, 2));
        const float mn0 = fmaxf(m0, mx0), mn1 = fmaxf(m1, mx1);
        const float f0 = __expf(m0 - mn0), f1 = __expf(m1 - mn1);
        m0 = mn0; m1 = mn1;
        float sum0 = 0.f, sum1 = 0.f;
#pragma unroll
        for (int nt = 0; nt < 8; nt++) {
            s4[nt][0] = __expf(s4[nt][0] - mn0);
            s4[nt][1] = __expf(s4[nt][1] - mn0);
            s4[nt][2] = __expf(s4[nt][2] - mn1);
            s4[nt][3] = __expf(s4[nt][3] - mn1);
            sum0 += s4[nt][0] + s4[nt][1];
            sum1 += s4[nt][2] + s4[nt][3];
        }
        sum0 += __shfl_xor_sync(0xffffffffu, sum0, 1);
        sum0 += __shfl_xor_sync(0xffffffffu, sum0, 2);
        sum1 += __shfl_xor_sync(0xffffffffu, sum1, 1);
        sum1 += __shfl_xor_sync(0xffffffffu, sum1, 2);
        l0 = l0 * f0 + sum0;
        l1 = l1 * f1 + sum1;
#pragma unroll
        for (int dt = 0; dt < 8; dt++) {
            o[dt][0] *= f0; o[dt][1] *= f0; o[dt][2] *= f1; o[dt][3] *= f1;
        }

        uint32_t ph[8][2], pl[8][2];
#pragma unroll
        for (int nt = 0; nt < 8; nt++) {
            bf16 h0 = __float2bfloat16(s4[nt][0]), h1 = __float2bfloat16(s4[nt][1]);
            bf16 h2 = __float2bfloat16(s4[nt][2]), h3 = __float2bfloat16(s4[nt][3]);
            ph[nt][0] = pack_bf16(__bfloat162float(h0), __bfloat162float(h1));
            ph[nt][1] = pack_bf16(__bfloat162float(h2), __bfloat162float(h3));
            pl[nt][0] = pack_bf16(s4[nt][0] - __bfloat162float(h0), s4[nt][1] - __bfloat162float(h1));
            pl[nt][1] = pack_bf16(s4[nt][2] - __bfloat162float(h2), s4[nt][3] - __bfloat162float(h3));
        }

#pragma unroll
        for (int ks = 0; ks < 4; ks++) {
            uint32_t pa_h[4] = { ph[2 * ks][0], ph[2 * ks][1], ph[2 * ks + 1][0], ph[2 * ks + 1][1] };
            uint32_t pa_l[4] = { pl[2 * ks][0], pl[2 * ks][1], pl[2 * ks + 1][0], pl[2 * ks + 1][1] };
#pragma unroll
            for (int dp = 0; dp < 4; dp++) {
                uint32_t vh4[4], vl4[4];
                uint32_t a = st + 2 * AT_TILE + (uint32_t)(16 * ks) * AT_STR + vRow + dp * 32;
                ldsm4t(vh4, a);
                ldsm4t(vl4, a + AT_TILE);
                mma_bf16(o[2 * dp],     pa_h, &vh4[0]);
                mma_bf16(o[2 * dp + 1], pa_h, &vh4[2]);
                mma_bf16(o[2 * dp],     pa_h, &vl4[0]);
                mma_bf16(o[2 * dp + 1], pa_h, &vl4[2]);
                mma_bf16(o[2 * dp],     pa_l, &vh4[0]);
                mma_bf16(o[2 * dp + 1], pa_l, &vh4[2]);
            }
        }

        if (c + 1 < 32) CP_WAIT0();
        __syncthreads();
    }

    const float inv0 = 1.f / l0, inv1 = 1.f / l1;
    const int r0 = q0 + wid * 16 + (lid >> 2);
    const int cc = (lid & 3) * 2;
#pragma unroll
    for (int dt = 0; dt < 8; dt++) {
        float v0 = o[dt][0] * inv0, v1 = o[dt][1] * inv0;
        float v2 = o[dt][2] * inv1, v3 = o[dt][3] * inv1;
        bf16 h0 = __float2bfloat16(v0), h1 = __float2bfloat16(v1);
        bf16 h2 = __float2bfloat16(v2), h3 = __float2bfloat16(v3);
        size_t off0 = ebase + (size_t)r0 * 1024 + dt * 8 + cc;
        size_t off1 = ebase + (size_t)(r0 + 8) * 1024 + dt * 8 + cc;
        *(uint32_t*)&Ch[off0] = pack_bf16(__bfloat162float(h0), __bfloat162float(h1));
        *(uint32_t*)&Cl[off0] = pack_bf16(v0 - __bfloat162float(h0), v1 - __bfloat162float(h1));
        *(uint32_t*)&Ch[off1] = pack_bf16(__bfloat162float(h2), __bfloat162float(h3));
        *(uint32_t*)&Cl[off1] = pack_bf16(v2 - __bfloat162float(h2), v3 - __bfloat162float(h3));
    }
}

// ---------------------------------------------------------------------------
extern "C" void kernel_launch(void* const* d_in, const int* in_sizes, int n_in,
                              void* d_out, int out_size)
{
    const float* X  = (const float*)d_in[0];
    const float* Wq = (const float*)d_in[1];
    const float* Wk = (const float*)d_in[2];
    const float* Wv = (const float*)d_in[3];
    const float* Wo = (const float*)d_in[4];
    float* out = (float*)d_out;

    bf16 *Ah, *Al, *Wh, *Wl, *Qh, *Ql, *Kh, *Kl, *Vh, *Vl;
    cudaGetSymbolAddress((void**)&Ah, g_Ah);
    cudaGetSymbolAddress((void**)&Al, g_Al);
    cudaGetSymbolAddress((void**)&Wh, g_Wh);
    cudaGetSymbolAddress((void**)&Wl, g_Wl);
    cudaGetSymbolAddress((void**)&Qh, g_Qh);
    cudaGetSymbolAddress((void**)&Ql, g_Ql);
    cudaGetSymbolAddress((void**)&Kh, g_Kh);
    cudaGetSymbolAddress((void**)&Kl, g_Kl);
    cudaGetSymbolAddress((void**)&Vh, g_Vh);
    cudaGetSymbolAddress((void**)&Vl, g_Vl);

    cudaFuncSetAttribute(gemm_tc_kernel, cudaFuncAttributeMaxDynamicSharedMemorySize, GEMM_SMEM);
    cudaFuncSetAttribute(attn_tc_kernel, cudaFuncAttributeMaxDynamicSharedMemorySize, AT_SMEM);

    const int totalBlocks = (NX_ + 4 * NW_) / 256;
    cvt_all<<<totalBlocks, 256>>>(X, Wq, Wk, Wv, Wo, Ah, Al, Wh, Wl);

    dim3 gqkv(1024 / 128, MTOT / 128, 3);
    gemm_tc_kernel<<<gqkv, 512, GEMM_SMEM>>>(
        Ah, Al,
        Wh + 0 * (size_t)NW_, Wl + 0 * (size_t)NW_,
        Wh + 1 * (size_t)NW_, Wl + 1 * (size_t)NW_,
        Wh + 2 * (size_t)NW_, Wl + 2 * (size_t)NW_,
        Qh, Ql, Kh, Kl, Vh, Vl,
        nullptr, 0.125f);

    dim3 gattn(S_ / 128, H_, B_);
    attn_tc_kernel<<<gattn, 256, AT_SMEM>>>(Qh, Ql, Kh, Kl, Vh, Vl, Ah, Al);

    dim3 go(1024 / 128, MTOT / 128, 1);
    gemm_tc_kernel<<<go, 512, GEMM_SMEM>>>(
        Ah, Al,
        Wh + 3 * (size_t)NW_, Wl + 3 * (size_t)NW_,
        Wh + 3 * (size_t)NW_, Wl + 3 * (size_t)NW_,
        Wh + 3 * (size_t)NW_, Wl + 3 * (size_t)NW_,
        Qh, Ql, Qh, Ql, Qh, Ql,
        out, 1.f);
}

// round 10
// speedup vs baseline: 1.0576x; 1.0576x over previous
#include <cuda_runtime.h>
#include <cuda_bf16.h>
#include <math.h>
#include <cstdint>

#define B_  4
#define S_  2048
#define D_  1024
#define H_  16
#define DK_ 64
#define MTOT (B_*S_)   // 8192
#define NX_  (MTOT * D_)      // 8388608
#define NW_  (D_ * D_)        // 1048576

typedef __nv_bfloat16 bf16;

__device__ bf16 g_Ah[(size_t)NX_];
__device__ bf16 g_Al[(size_t)NX_];
__device__ bf16 g_Wh[4 * (size_t)NW_];
__device__ bf16 g_Wl[4 * (size_t)NW_];
__device__ bf16 g_Qh[(size_t)NX_];
__device__ bf16 g_Ql[(size_t)NX_];
__device__ bf16 g_Kh[(size_t)NX_];
__device__ bf16 g_Kl[(size_t)NX_];
__device__ bf16 g_Vh[(size_t)NX_];
__device__ bf16 g_Vl[(size_t)NX_];

__device__ __forceinline__ uint32_t smem_to_u32(const void* p) {
    uint32_t a;
    asm("{ .reg .u64 t; cvta.to.shared.u64 t, %1; cvt.u32.u64 %0, t; }" : "=r"(a) : "l"(p));
    return a;
}
__device__ __forceinline__ void ldsm4(uint32_t* r, uint32_t addr) {
    asm volatile("ldmatrix.sync.aligned.m8n8.x4.shared.b16 {%0,%1,%2,%3}, [%4];"
                 : "=r"(r[0]), "=r"(r[1]), "=r"(r[2]), "=r"(r[3]) : "r"(addr));
}
__device__ __forceinline__ void ldsm4t(uint32_t* r, uint32_t addr) {
    asm volatile("ldmatrix.sync.aligned.m8n8.x4.trans.shared.b16 {%0,%1,%2,%3}, [%4];"
                 : "=r"(r[0]), "=r"(r[1]), "=r"(r[2]), "=r"(r[3]) : "r"(addr));
}
__device__ __forceinline__ void mma_bf16(float* d, const uint32_t* a, const uint32_t* b) {
    asm volatile("mma.sync.aligned.m16n8k16.row.col.f32.bf16.bf16.f32 "
                 "{%0,%1,%2,%3}, {%4,%5,%6,%7}, {%8,%9}, {%0,%1,%2,%3};"
                 : "+f"(d[0]), "+f"(d[1]), "+f"(d[2]), "+f"(d[3])
                 : "r"(a[0]), "r"(a[1]), "r"(a[2]), "r"(a[3]), "r"(b[0]), "r"(b[1]));
}
#define CP_ASYNC16(s, g) \
    asm volatile("cp.async.cg.shared.global [%0], [%1], 16;" :: "r"(s), "l"(g))
#define CP_COMMIT()  asm volatile("cp.async.commit_group;" ::: "memory")
#define CP_WAIT0()   asm volatile("cp.async.wait_group 0;" ::: "memory")
#define CP_WAIT1()   asm volatile("cp.async.wait_group 1;" ::: "memory")

__device__ __forceinline__ uint32_t pack_bf16(float a, float b) {
    __nv_bfloat162 t = __floats2bfloat162_rn(a, b);
    return *(uint32_t*)&t;
}

// ---------------------------------------------------------------------------
__global__ void cvt_all(const float* __restrict__ X,  const float* __restrict__ Wq,
                        const float* __restrict__ Wk, const float* __restrict__ Wv,
                        const float* __restrict__ Wo,
                        bf16* __restrict__ Ah, bf16* __restrict__ Al,
                        bf16* __restrict__ Wh, bf16* __restrict__ Wl)
{
    size_t i = (size_t)blockIdx.x * 256 + threadIdx.x;
    const float* src; bf16 *h, *l; size_t off;
    if (i < (size_t)NX_) {
        src = X; h = Ah; l = Al; off = i;
    } else {
        size_t j = i - NX_;
        int w = (int)(j >> 20);
        off = j & (NW_ - 1);
        src = (w == 0) ? Wq : (w == 1) ? Wk : (w == 2) ? Wv : Wo;
        h = Wh + (size_t)w * NW_;
        l = Wl + (size_t)w * NW_;
    }
    float v = src[off];
    bf16 hh = __float2bfloat16(v);
    h[off] = hh;
    l[off] = __float2bfloat16(v - __bfloat162float(hh));
}

// ---------------------------------------------------------------------------
// bf16x3 GEMM, mma.sync. 256 threads (8 warps, warp tile 32x64), CTA 128x128,
// K-chunk 32, 2-stage cp.async, 2 CTAs/SM so LDSM/MMA phases interleave
// across CTAs instead of convoying behind one CTA's barrier.
// ---------------------------------------------------------------------------
#define KCg       32
#define GSTR      80                        // bytes per smem row (64 data + 16 pad)
#define GTILE     (128 * GSTR)              // 10240
#define GSTAGE    (4 * GTILE)               // 40960 (Ah,Al,Bh,Bl)
#define GEMM_SMEM (2 * GSTAGE)              // 81920

__global__ __launch_bounds__(256, 2)
void gemm_tc_kernel(const bf16* __restrict__ Ah, const bf16* __restrict__ Al,
                    const bf16* __restrict__ B0h, const bf16* __restrict__ B0l,
                    const bf16* __restrict__ B1h, const bf16* __restrict__ B1l,
                    const bf16* __restrict__ B2h, const bf16* __restrict__ B2l,
                    bf16* __restrict__ Yh0, bf16* __restrict__ Yl0,
                    bf16* __restrict__ Yh1, bf16* __restrict__ Yl1,
                    bf16* __restrict__ Yh2, bf16* __restrict__ Yl2,
                    float* __restrict__ Yf, float sc0)
{
    const bf16* Bh = (blockIdx.z == 0) ? B0h : (blockIdx.z == 1) ? B1h : B2h;
    const bf16* Bl = (blockIdx.z == 0) ? B0l : (blockIdx.z == 1) ? B1l : B2l;
    bf16* Yh = (blockIdx.z == 0) ? Yh0 : (blockIdx.z == 1) ? Yh1 : Yh2;
    bf16* Yl = (blockIdx.z == 0) ? Yl0 : (blockIdx.z == 1) ? Yl1 : Yl2;
    const float osc = (blockIdx.z == 0) ? sc0 : 1.f;

    extern __shared__ char smem[];
    const uint32_t sb = smem_to_u32(smem);
    const int tid = threadIdx.x;
    const int wid = tid >> 5;
    const int lid = tid & 31;
    const int wm  = wid >> 1;     // 0..3
    const int wn  = wid & 1;      // 0..1
    const int m0  = blockIdx.y * 128;
    const int n0  = blockIdx.x * 128;

    // gmem->smem mapping: per tile 512 x 16B; thread handles idx = tid, tid+256
    const int row0 = tid >> 2, c0 = (tid & 3);
    const int row1 = (tid + 256) >> 2, c1 = ((tid + 256) & 3);
    const uint32_t so0 = (uint32_t)row0 * GSTR + c0 * 16;
    const uint32_t so1 = (uint32_t)row1 * GSTR + c1 * 16;
    const size_t gA0 = (size_t)(m0 + row0) * 1024 + c0 * 8;
    const size_t gA1 = (size_t)(m0 + row1) * 1024 + c1 * 8;
    const size_t gB0 = (size_t)(n0 + row0) * 1024 + c0 * 8;
    const size_t gB1 = (size_t)(n0 + row1) * 1024 + c1 * 8;

    const uint32_t aRow = (uint32_t)(wm * 32 + (lid & 15)) * GSTR + ((lid & 16) ? 16u : 0u);
    const uint32_t bRow = (uint32_t)(wn * 64 + (lid & 7) + ((lid & 16) ? 8 : 0)) * GSTR
                          + ((lid & 8) ? 16u : 0u);

    float acc[2][8][4];
#pragma unroll
    for (int mb = 0; mb < 2; mb++)
#pragma unroll
        for (int nb = 0; nb < 8; nb++)
#pragma unroll
            for (int q = 0; q < 4; q++) acc[mb][nb][q] = 0.f;

    auto issue = [&](int stage, int c) {
        const uint32_t st = sb + (uint32_t)stage * GSTAGE;
        const size_t ko = (size_t)c * KCg;
        CP_ASYNC16(st + 0 * GTILE + so0, Ah + gA0 + ko);
        CP_ASYNC16(st + 0 * GTILE + so1, Ah + gA1 + ko);
        CP_ASYNC16(st + 1 * GTILE + so0, Al + gA0 + ko);
        CP_ASYNC16(st + 1 * GTILE + so1, Al + gA1 + ko);
        CP_ASYNC16(st + 2 * GTILE + so0, Bh + gB0 + ko);
        CP_ASYNC16(st + 2 * GTILE + so1, Bh + gB1 + ko);
        CP_ASYNC16(st + 3 * GTILE + so0, Bl + gB0 + ko);
        CP_ASYNC16(st + 3 * GTILE + so1, Bl + gB1 + ko);
    };

    issue(0, 0); CP_COMMIT();

    for (int c = 0; c < 32; c++) {
        if (c + 1 < 32) { issue((c + 1) & 1, c + 1); CP_COMMIT(); CP_WAIT1(); }
        else            { CP_WAIT0(); }
        __syncthreads();

        const uint32_t st = sb + (uint32_t)(c & 1) * GSTAGE;
#pragma unroll
        for (int ks = 0; ks < 2; ks++) {
            const uint32_t kb = (uint32_t)ks * 32;
            uint32_t fa[2][4], fbh[4][4];
#pragma unroll
            for (int mb = 0; mb < 2; mb++)
                ldsm4(fa[mb], st + 0 * GTILE + aRow + (uint32_t)mb * (16 * GSTR) + kb);
#pragma unroll
            for (int g = 0; g < 4; g++)
                ldsm4(fbh[g], st + 2 * GTILE + bRow + (uint32_t)g * (16 * GSTR) + kb);
            // pass 1: hi*hi
#pragma unroll
            for (int mb = 0; mb < 2; mb++)
#pragma unroll
                for (int nb = 0; nb < 8; nb++)
                    mma_bf16(acc[mb][nb], fa[mb], &fbh[nb >> 1][(nb & 1) * 2]);
            // pass 2: hi*lo (load fbl late to bound register pressure)
            {
                uint32_t fbl[4][4];
#pragma unroll
                for (int g = 0; g < 4; g++)
                    ldsm4(fbl[g], st + 3 * GTILE + bRow + (uint32_t)g * (16 * GSTR) + kb);
#pragma unroll
                for (int mb = 0; mb < 2; mb++)
#pragma unroll
                    for (int nb = 0; nb < 8; nb++)
                        mma_bf16(acc[mb][nb], fa[mb], &fbl[nb >> 1][(nb & 1) * 2]);
            }
            // pass 3: lo*hi
            {
                uint32_t fal[2][4];
#pragma unroll
                for (int mb = 0; mb < 2; mb++)
                    ldsm4(fal[mb], st + 1 * GTILE + aRow + (uint32_t)mb * (16 * GSTR) + kb);
#pragma unroll
                for (int mb = 0; mb < 2; mb++)
#pragma unroll
                    for (int nb = 0; nb < 8; nb++)
                        mma_bf16(acc[mb][nb], fal[mb], &fbh[nb >> 1][(nb & 1) * 2]);
            }
        }
        __syncthreads();   // stage (c&1) reused at iteration c+1's issue
    }

    const int rr = lid >> 2;
    const int cc = (lid & 3) * 2;
    if (Yf) {
#pragma unroll
        for (int mb = 0; mb < 2; mb++) {
            const int row = m0 + wm * 32 + mb * 16 + rr;
#pragma unroll
            for (int nb = 0; nb < 8; nb++) {
                const int col = n0 + wn * 64 + nb * 8 + cc;
                *(float2*)&Yf[(size_t)row * 1024 + col]       = make_float2(acc[mb][nb][0], acc[mb][nb][1]);
                *(float2*)&Yf[(size_t)(row + 8) * 1024 + col] = make_float2(acc[mb][nb][2], acc[mb][nb][3]);
            }
        }
    } else {
#pragma unroll
        for (int mb = 0; mb < 2; mb++) {
            const int row = m0 + wm * 32 + mb * 16 + rr;
#pragma unroll
            for (int nb = 0; nb < 8; nb++) {
                const int col = n0 + wn * 64 + nb * 8 + cc;
#pragma unroll
                for (int half = 0; half < 2; half++) {
                    float v0 = acc[mb][nb][half * 2 + 0] * osc;
                    float v1 = acc[mb][nb][half * 2 + 1] * osc;
                    bf16 h0 = __float2bfloat16(v0), h1 = __float2bfloat16(v1);
                    float l0 = v0 - __bfloat162float(h0), l1 = v1 - __bfloat162float(h1);
                    size_t off = (size_t)(row + half * 8) * 1024 + col;
                    *(uint32_t*)&Yh[off] = pack_bf16(__bfloat162float(h0), __bfloat162float(h1));
                    *(uint32_t*)&Yl[off] = pack_bf16(l0, l1);
                }
            }
        }
    }
}

// ---------------------------------------------------------------------------
// Flash attention, mma.sync bf16x3 (unchanged from passing R9 kernel)
// ---------------------------------------------------------------------------
#define AT_STR   144
#define AT_TILE  (64 * AT_STR)
#define AT_STAGE (4 * AT_TILE)
#define AT_QOFF  (2 * AT_STAGE)
#define AT_SMEM  (AT_QOFF + 2 * 128 * AT_STR)   // 110592

__global__ __launch_bounds__(256)
void attn_tc_kernel(const bf16* __restrict__ Qh, const bf16* __restrict__ Ql,
                    const bf16* __restrict__ Kh, const bf16* __restrict__ Kl,
                    const bf16* __restrict__ Vh, const bf16* __restrict__ Vl,
                    bf16* __restrict__ Ch, bf16* __restrict__ Cl)
{
    extern __shared__ char smem[];
    const uint32_t sb = smem_to_u32(smem);
    const int tid = threadIdx.x;
    const int wid = tid >> 5;
    const int lid = tid & 31;
    const int q0  = blockIdx.x * 128;
    const int h   = blockIdx.y;
    const int b   = blockIdx.z;
    const size_t ebase = ((size_t)b * S_) * D_ + (size_t)h * DK_;

    {
#pragma unroll
        for (int l = 0; l < 4; l++) {
            int idx = tid + l * 256;
            int row = idx >> 3, c8 = idx & 7;
            size_t g = ebase + (size_t)(q0 + row) * 1024 + c8 * 8;
            uint32_t s = sb + AT_QOFF + (uint32_t)row * AT_STR + c8 * 16;
            CP_ASYNC16(s, Qh + g);
            CP_ASYNC16(s + 128 * AT_STR, Ql + g);
        }
#pragma unroll
        for (int l = 0; l < 2; l++) {
            int idx = tid + l * 256;
            int row = idx >> 3, c8 = idx & 7;
            size_t g = ebase + (size_t)row * 1024 + c8 * 8;
            uint32_t s = sb + (uint32_t)row * AT_STR + c8 * 16;
            CP_ASYNC16(s + 0 * AT_TILE, Kh + g);
            CP_ASYNC16(s + 1 * AT_TILE, Kl + g);
            CP_ASYNC16(s + 2 * AT_TILE, Vh + g);
            CP_ASYNC16(s + 3 * AT_TILE, Vl + g);
        }
        CP_COMMIT();
        CP_WAIT0();
        __syncthreads();
    }

    const uint32_t qAddrBase = sb + AT_QOFF + (uint32_t)(wid * 16 + (lid & 15)) * AT_STR
                               + ((lid & 16) ? 16u : 0u);
    uint32_t qh[4][4];
#pragma unroll
    for (int ks = 0; ks < 4; ks++) ldsm4(qh[ks], qAddrBase + ks * 32);

    float m0 = -INFINITY, m1 = -INFINITY, l0 = 0.f, l1 = 0.f;
    float o[8][4];
#pragma unroll
    for (int dt = 0; dt < 8; dt++)
#pragma unroll
        for (int q = 0; q < 4; q++) o[dt][q] = 0.f;

    const uint32_t kRow = (uint32_t)((lid & 7) + ((lid & 16) ? 8 : 0)) * AT_STR + ((lid & 8) ? 16u : 0u);
    const uint32_t vRow = (uint32_t)(lid & 15) * AT_STR + ((lid & 16) ? 16u : 0u);

    for (int c = 0; c < 32; c++) {
        const uint32_t st = sb + (uint32_t)(c & 1) * AT_STAGE;

        if (c + 1 < 32) {
            const uint32_t sn = sb + (uint32_t)((c + 1) & 1) * AT_STAGE;
            const int ks0 = (c + 1) * 64;
#pragma unroll
            for (int l = 0; l < 2; l++) {
                int idx = tid + l * 256;
                int row = idx >> 3, c8 = idx & 7;
                size_t g = ebase + (size_t)(ks0 + row) * 1024 + c8 * 8;
                uint32_t s = sn + (uint32_t)row * AT_STR + c8 * 16;
                CP_ASYNC16(s + 0 * AT_TILE, Kh + g);
                CP_ASYNC16(s + 1 * AT_TILE, Kl + g);
                CP_ASYNC16(s + 2 * AT_TILE, Vh + g);
                CP_ASYNC16(s + 3 * AT_TILE, Vl + g);
            }
            CP_COMMIT();
        }

        float s4[8][4];
#pragma unroll
        for (int nt = 0; nt < 8; nt++)
#pragma unroll
            for (int q = 0; q < 4; q++) s4[nt][q] = 0.f;

#pragma unroll
        for (int ks = 0; ks < 4; ks++) {
            uint32_t bh[4][4], bl[4][4], qlr[4];
#pragma unroll
            for (int g = 0; g < 4; g++) {
                uint32_t a = st + (uint32_t)(16 * g) * AT_STR + kRow + ks * 32;
                ldsm4(bh[g], a);
                ldsm4(bl[g], a + AT_TILE);
            }
            ldsm4(qlr, qAddrBase + 128 * AT_STR + ks * 32);
#pragma unroll
            for (int nt = 0; nt < 8; nt++)
                mma_bf16(s4[nt], qh[ks], &bh[nt >> 1][(nt & 1) * 2]);
#pragma unroll
            for (int nt = 0; nt < 8; nt++)
                mma_bf16(s4[nt], qh[ks], &bl[nt >> 1][(nt & 1) * 2]);
#pragma unroll
            for (int nt = 0; nt < 8; nt++)
                mma_bf16(s4[nt], qlr,    &bh[nt >> 1][(nt & 1) * 2]);
        }

        float mx0 = -INFINITY, mx1 = -INFINITY;
#pragma unroll
        for (int nt = 0; nt < 8; nt++) {
            mx0 = fmaxf(mx0, fmaxf(s4[nt][0], s4[nt][1]));
            mx1 = fmaxf(mx1, fmaxf(s4[nt][2], s4[nt][3]));
        }
        mx0 = fmaxf(mx0, __shfl_xor_sync(0xffffffffu, mx0, 1));
        mx0 = fmaxf(mx0, __shfl_xor_sync(0xffffffffu, mx0, 2));
        mx1 = fmaxf(mx1, __shfl_xor_sync(0xffffffffu, mx1, 1));
        mx1 = fmaxf(mx1, __shfl_xor_sync(0xffffffffu, mx1, 2));
        const float mn0 = fmaxf(m0, mx0), mn1 = fmaxf(m1, mx1);
        const float f0 = __expf(m0 - mn0), f1 = __expf(m1 - mn1);
        m0 = mn0; m1 = mn1;
        float sum0 = 0.f, sum1 = 0.f;
#pragma unroll
        for (int nt = 0; nt < 8; nt++) {
            s4[nt][0] = __expf(s4[nt][0] - mn0);
            s4[nt][1] = __expf(s4[nt][1] - mn0);
            s4[nt][2] = __expf(s4[nt][2] - mn1);
            s4[nt][3] = __expf(s4[nt][3] - mn1);
            sum0 += s4[nt][0] + s4[nt][1];
            sum1 += s4[nt][2] + s4[nt][3];
        }
        sum0 += __shfl_xor_sync(0xffffffffu, sum0, 1);
        sum0 += __shfl_xor_sync(0xffffffffu, sum0, 2);
        sum1 += __shfl_xor_sync(0xffffffffu, sum1, 1);
        sum1 += __shfl_xor_sync(0xffffffffu, sum1, 2);
        l0 = l0 * f0 + sum0;
        l1 = l1 * f1 + sum1;
#pragma unroll
        for (int dt = 0; dt < 8; dt++) {
            o[dt][0] *= f0; o[dt][1] *= f0; o[dt][2] *= f1; o[dt][3] *= f1;
        }

        uint32_t ph[8][2], pl[8][2];
#pragma unroll
        for (int nt = 0; nt < 8; nt++) {
            bf16 h0 = __float2bfloat16(s4[nt][0]), h1 = __float2bfloat16(s4[nt][1]);
            bf16 h2 = __float2bfloat16(s4[nt][2]), h3 = __float2bfloat16(s4[nt][3]);
            ph[nt][0] = pack_bf16(__bfloat162float(h0), __bfloat162float(h1));
            ph[nt][1] = pack_bf16(__bfloat162float(h2), __bfloat162float(h3));
            pl[nt][0] = pack_bf16(s4[nt][0] - __bfloat162float(h0), s4[nt][1] - __bfloat162float(h1));
            pl[nt][1] = pack_bf16(s4[nt][2] - __bfloat162float(h2), s4[nt][3] - __bfloat162float(h3));
        }

#pragma unroll
        for (int ks = 0; ks < 4; ks++) {
            uint32_t pa_h[4] = { ph[2 * ks][0], ph[2 * ks][1], ph[2 * ks + 1][0], ph[2 * ks + 1][1] };
            uint32_t pa_l[4] = { pl[2 * ks][0], pl[2 * ks][1], pl[2 * ks + 1][0], pl[2 * ks + 1][1] };
#pragma unroll
            for (int dp = 0; dp < 4; dp++) {
                uint32_t vh4[4], vl4[4];
                uint32_t a = st + 2 * AT_TILE + (uint32_t)(16 * ks) * AT_STR + vRow + dp * 32;
                ldsm4t(vh4, a);
                ldsm4t(vl4, a + AT_TILE);
                mma_bf16(o[2 * dp],     pa_h, &vh4[0]);
                mma_bf16(o[2 * dp + 1], pa_h, &vh4[2]);
                mma_bf16(o[2 * dp],     pa_h, &vl4[0]);
                mma_bf16(o[2 * dp + 1], pa_h, &vl4[2]);
                mma_bf16(o[2 * dp],     pa_l, &vh4[0]);
                mma_bf16(o[2 * dp + 1], pa_l, &vh4[2]);
            }
        }

        if (c + 1 < 32) CP_WAIT0();
        __syncthreads();
    }

    const float inv0 = 1.f / l0, inv1 = 1.f / l1;
    const int r0 = q0 + wid * 16 + (lid >> 2);
    const int cc = (lid & 3) * 2;
#pragma unroll
    for (int dt = 0; dt < 8; dt++) {
        float v0 = o[dt][0] * inv0, v1 = o[dt][1] * inv0;
        float v2 = o[dt][2] * inv1, v3 = o[dt][3] * inv1;
        bf16 h0 = __float2bfloat16(v0), h1 = __float2bfloat16(v1);
        bf16 h2 = __float2bfloat16(v2), h3 = __float2bfloat16(v3);
        size_t off0 = ebase + (size_t)r0 * 1024 + dt * 8 + cc;
        size_t off1 = ebase + (size_t)(r0 + 8) * 1024 + dt * 8 + cc;
        *(uint32_t*)&Ch[off0] = pack_bf16(__bfloat162float(h0), __bfloat162float(h1));
        *(uint32_t*)&Cl[off0] = pack_bf16(v0 - __bfloat162float(h0), v1 - __bfloat162float(h1));
        *(uint32_t*)&Ch[off1] = pack_bf16(__bfloat162float(h2), __bfloat162float(h3));
        *(uint32_t*)&Cl[off1] = pack_bf16(v2 - __bfloat162float(h2), v3 - __bfloat162float(h3));
    }
}

// ---------------------------------------------------------------------------
extern "C" void kernel_launch(void* const* d_in, const int* in_sizes, int n_in,
                              void* d_out, int out_size)
{
    const float* X  = (const float*)d_in[0];
    const float* Wq = (const float*)d_in[1];
    const float* Wk = (const float*)d_in[2];
    const float* Wv = (const float*)d_in[3];
    const float* Wo = (const float*)d_in[4];
    float* out = (float*)d_out;

    bf16 *Ah, *Al, *Wh, *Wl, *Qh, *Ql, *Kh, *Kl, *Vh, *Vl;
    cudaGetSymbolAddress((void**)&Ah, g_Ah);
    cudaGetSymbolAddress((void**)&Al, g_Al);
    cudaGetSymbolAddress((void**)&Wh, g_Wh);
    cudaGetSymbolAddress((void**)&Wl, g_Wl);
    cudaGetSymbolAddress((void**)&Qh, g_Qh);
    cudaGetSymbolAddress((void**)&Ql, g_Ql);
    cudaGetSymbolAddress((void**)&Kh, g_Kh);
    cudaGetSymbolAddress((void**)&Kl, g_Kl);
    cudaGetSymbolAddress((void**)&Vh, g_Vh);
    cudaGetSymbolAddress((void**)&Vl, g_Vl);

    cudaFuncSetAttribute(gemm_tc_kernel, cudaFuncAttributeMaxDynamicSharedMemorySize, GEMM_SMEM);
    cudaFuncSetAttribute(attn_tc_kernel, cudaFuncAttributeMaxDynamicSharedMemorySize, AT_SMEM);

    const int totalBlocks = (NX_ + 4 * NW_) / 256;
    cvt_all<<<totalBlocks, 256>>>(X, Wq, Wk, Wv, Wo, Ah, Al, Wh, Wl);

    dim3 gqkv(1024 / 128, MTOT / 128, 3);
    gemm_tc_kernel<<<gqkv, 256, GEMM_SMEM>>>(
        Ah, Al,
        Wh + 0 * (size_t)NW_, Wl + 0 * (size_t)NW_,
        Wh + 1 * (size_t)NW_, Wl + 1 * (size_t)NW_,
        Wh + 2 * (size_t)NW_, Wl + 2 * (size_t)NW_,
        Qh, Ql, Kh, Kl, Vh, Vl,
        nullptr, 0.125f);

    dim3 gattn(S_ / 128, H_, B_);
    attn_tc_kernel<<<gattn, 256, AT_SMEM>>>(Qh, Ql, Kh, Kl, Vh, Vl, Ah, Al);

    dim3 go(1024 / 128, MTOT / 128, 1);
    gemm_tc_kernel<<<go, 256, GEMM_SMEM>>>(
        Ah, Al,
        Wh + 3 * (size_t)NW_, Wl + 3 * (size_t)NW_,
        Wh + 3 * (size_t)NW_, Wl + 3 * (size_t)NW_,
        Wh + 3 * (size_t)NW_, Wl + 3 * (size_t)NW_,
        Qh, Ql, Qh, Ql, Qh, Ql,
        out, 1.f);
}

// round 13
// speedup vs baseline: 1.0662x; 1.0081x over previous
#include <cuda_runtime.h>
#include <cuda_bf16.h>
#include <math.h>
#include <cstdint>

#define B_  4
#define S_  2048
#define D_  1024
#define H_  16
#define DK_ 64
#define MTOT (B_*S_)   // 8192
#define NX_  (MTOT * D_)      // 8388608
#define NW_  (D_ * D_)        // 1048576

typedef __nv_bfloat16 bf16;

__device__ bf16 g_Ah[(size_t)NX_];
__device__ bf16 g_Al[(size_t)NX_];
__device__ bf16 g_Wh[4 * (size_t)NW_];
__device__ bf16 g_Wl[4 * (size_t)NW_];
__device__ bf16 g_Qh[(size_t)NX_];
__device__ bf16 g_Ql[(size_t)NX_];
__device__ bf16 g_Kh[(size_t)NX_];
__device__ bf16 g_Kl[(size_t)NX_];
__device__ bf16 g_Vh[(size_t)NX_];
__device__ bf16 g_Vl[(size_t)NX_];

__device__ __forceinline__ uint32_t smem_to_u32(const void* p) {
    uint32_t a;
    asm("{ .reg .u64 t; cvta.to.shared.u64 t, %1; cvt.u32.u64 %0, t; }" : "=r"(a) : "l"(p));
    return a;
}
__device__ __forceinline__ void ldsm4(uint32_t* r, uint32_t addr) {
    asm volatile("ldmatrix.sync.aligned.m8n8.x4.shared.b16 {%0,%1,%2,%3}, [%4];"
                 : "=r"(r[0]), "=r"(r[1]), "=r"(r[2]), "=r"(r[3]) : "r"(addr));
}
__device__ __forceinline__ void ldsm4t(uint32_t* r, uint32_t addr) {
    asm volatile("ldmatrix.sync.aligned.m8n8.x4.trans.shared.b16 {%0,%1,%2,%3}, [%4];"
                 : "=r"(r[0]), "=r"(r[1]), "=r"(r[2]), "=r"(r[3]) : "r"(addr));
}
__device__ __forceinline__ void mma_bf16(float* d, const uint32_t* a, const uint32_t* b) {
    asm volatile("mma.sync.aligned.m16n8k16.row.col.f32.bf16.bf16.f32 "
                 "{%0,%1,%2,%3}, {%4,%5,%6,%7}, {%8,%9}, {%0,%1,%2,%3};"
                 : "+f"(d[0]), "+f"(d[1]), "+f"(d[2]), "+f"(d[3])
                 : "r"(a[0]), "r"(a[1]), "r"(a[2]), "r"(a[3]), "r"(b[0]), "r"(b[1]));
}
#define CP_ASYNC16(s, g) \
    asm volatile("cp.async.cg.shared.global [%0], [%1], 16;" :: "r"(s), "l"(g))
#define CP_COMMIT()  asm volatile("cp.async.commit_group;" ::: "memory")
#define CP_WAIT0()   asm volatile("cp.async.wait_group 0;" ::: "memory")

__device__ __forceinline__ uint32_t pack_bf16(float a, float b) {
    __nv_bfloat162 t = __floats2bfloat162_rn(a, b);
    return *(uint32_t*)&t;
}

// ---------------------------------------------------------------------------
__global__ void cvt_all(const float* __restrict__ X,  const float* __restrict__ Wq,
                        const float* __restrict__ Wk, const float* __restrict__ Wv,
                        const float* __restrict__ Wo,
                        bf16* __restrict__ Ah, bf16* __restrict__ Al,
                        bf16* __restrict__ Wh, bf16* __restrict__ Wl)
{
    size_t i = (size_t)blockIdx.x * 256 + threadIdx.x;
    const float* src; bf16 *h, *l; size_t off;
    if (i < (size_t)NX_) {
        src = X; h = Ah; l = Al; off = i;
    } else {
        size_t j = i - NX_;
        int w = (int)(j >> 20);
        off = j & (NW_ - 1);
        src = (w == 0) ? Wq : (w == 1) ? Wk : (w == 2) ? Wv : Wo;
        h = Wh + (size_t)w * NW_;
        l = Wl + (size_t)w * NW_;
    }
    float v = src[off];
    bf16 hh = __float2bfloat16(v);
    h[off] = hh;
    l[off] = __float2bfloat16(v - __bfloat162float(hh));
}

// ---------------------------------------------------------------------------
// bf16x3 GEMM, mma.sync. 256 threads (8 warps, warp tile 32x64), CTA 128x128,
// K-chunk 32, 2-stage cp.async, ONE barrier per chunk, 2 CTAs/SM.
// ---------------------------------------------------------------------------
#define KCg       32
#define GSTR      80
#define GTILE     (128 * GSTR)              // 10240
#define GSTAGE    (4 * GTILE)               // 40960
#define GEMM_SMEM (2 * GSTAGE)              // 81920

__global__ __launch_bounds__(256, 2)
void gemm_tc_kernel(const bf16* __restrict__ Ah, const bf16* __restrict__ Al,
                    const bf16* __restrict__ B0h, const bf16* __restrict__ B0l,
                    const bf16* __restrict__ B1h, const bf16* __restrict__ B1l,
                    const bf16* __restrict__ B2h, const bf16* __restrict__ B2l,
                    bf16* __restrict__ Yh0, bf16* __restrict__ Yl0,
                    bf16* __restrict__ Yh1, bf16* __restrict__ Yl1,
                    bf16* __restrict__ Yh2, bf16* __restrict__ Yl2,
                    float* __restrict__ Yf, float sc0)
{
    const bf16* Bh = (blockIdx.z == 0) ? B0h : (blockIdx.z == 1) ? B1h : B2h;
    const bf16* Bl = (blockIdx.z == 0) ? B0l : (blockIdx.z == 1) ? B1l : B2l;
    bf16* Yh = (blockIdx.z == 0) ? Yh0 : (blockIdx.z == 1) ? Yh1 : Yh2;
    bf16* Yl = (blockIdx.z == 0) ? Yl0 : (blockIdx.z == 1) ? Yl1 : Yl2;
    const float osc = (blockIdx.z == 0) ? sc0 : 1.f;

    extern __shared__ char smem[];
    const uint32_t sb = smem_to_u32(smem);
    const int tid = threadIdx.x;
    const int wid = tid >> 5;
    const int lid = tid & 31;
    const int wm  = wid >> 1;
    const int wn  = wid & 1;
    const int m0  = blockIdx.y * 128;
    const int n0  = blockIdx.x * 128;

    const int row0 = tid >> 2, c0 = (tid & 3);
    const int row1 = (tid + 256) >> 2, c1 = ((tid + 256) & 3);
    const uint32_t so0 = (uint32_t)row0 * GSTR + c0 * 16;
    const uint32_t so1 = (uint32_t)row1 * GSTR + c1 * 16;
    const size_t gA0 = (size_t)(m0 + row0) * 1024 + c0 * 8;
    const size_t gA1 = (size_t)(m0 + row1) * 1024 + c1 * 8;
    const size_t gB0 = (size_t)(n0 + row0) * 1024 + c0 * 8;
    const size_t gB1 = (size_t)(n0 + row1) * 1024 + c1 * 8;

    const uint32_t aRow = (uint32_t)(wm * 32 + (lid & 15)) * GSTR + ((lid & 16) ? 16u : 0u);
    const uint32_t bRow = (uint32_t)(wn * 64 + (lid & 7) + ((lid & 16) ? 8 : 0)) * GSTR
                          + ((lid & 8) ? 16u : 0u);

    float acc[2][8][4];
#pragma unroll
    for (int mb = 0; mb < 2; mb++)
#pragma unroll
        for (int nb = 0; nb < 8; nb++)
#pragma unroll
            for (int q = 0; q < 4; q++) acc[mb][nb][q] = 0.f;

    auto issue = [&](int stage, int c) {
        const uint32_t st = sb + (uint32_t)stage * GSTAGE;
        const size_t ko = (size_t)c * KCg;
        CP_ASYNC16(st + 0 * GTILE + so0, Ah + gA0 + ko);
        CP_ASYNC16(st + 0 * GTILE + so1, Ah + gA1 + ko);
        CP_ASYNC16(st + 1 * GTILE + so0, Al + gA0 + ko);
        CP_ASYNC16(st + 1 * GTILE + so1, Al + gA1 + ko);
        CP_ASYNC16(st + 2 * GTILE + so0, Bh + gB0 + ko);
        CP_ASYNC16(st + 2 * GTILE + so1, Bh + gB1 + ko);
        CP_ASYNC16(st + 3 * GTILE + so0, Bl + gB0 + ko);
        CP_ASYNC16(st + 3 * GTILE + so1, Bl + gB1 + ko);
    };

    issue(0, 0); CP_COMMIT();

    for (int c = 0; c < 32; c++) {
        // one barrier per chunk: wait for chunk c data; readers of the other
        // stage finished before this same barrier at iteration c-1, so issuing
        // chunk c+1 into it after the barrier is WAR-safe.
        CP_WAIT0();
        __syncthreads();
        if (c + 1 < 32) { issue((c + 1) & 1, c + 1); CP_COMMIT(); }

        const uint32_t st = sb + (uint32_t)(c & 1) * GSTAGE;
#pragma unroll
        for (int ks = 0; ks < 2; ks++) {
            const uint32_t kb = (uint32_t)ks * 32;
            uint32_t fa[2][4], fbh[4][4];
#pragma unroll
            for (int mb = 0; mb < 2; mb++)
                ldsm4(fa[mb], st + 0 * GTILE + aRow + (uint32_t)mb * (16 * GSTR) + kb);
#pragma unroll
            for (int g = 0; g < 4; g++)
                ldsm4(fbh[g], st + 2 * GTILE + bRow + (uint32_t)g * (16 * GSTR) + kb);
#pragma unroll
            for (int mb = 0; mb < 2; mb++)
#pragma unroll
                for (int nb = 0; nb < 8; nb++)
                    mma_bf16(acc[mb][nb], fa[mb], &fbh[nb >> 1][(nb & 1) * 2]);
            {
                uint32_t fbl[4][4];
#pragma unroll
                for (int g = 0; g < 4; g++)
                    ldsm4(fbl[g], st + 3 * GTILE + bRow + (uint32_t)g * (16 * GSTR) + kb);
#pragma unroll
                for (int mb = 0; mb < 2; mb++)
#pragma unroll
                    for (int nb = 0; nb < 8; nb++)
                        mma_bf16(acc[mb][nb], fa[mb], &fbl[nb >> 1][(nb & 1) * 2]);
            }
            {
                uint32_t fal[2][4];
#pragma unroll
                for (int mb = 0; mb < 2; mb++)
                    ldsm4(fal[mb], st + 1 * GTILE + aRow + (uint32_t)mb * (16 * GSTR) + kb);
#pragma unroll
                for (int mb = 0; mb < 2; mb++)
#pragma unroll
                    for (int nb = 0; nb < 8; nb++)
                        mma_bf16(acc[mb][nb], fal[mb], &fbh[nb >> 1][(nb & 1) * 2]);
            }
        }
    }

    const int rr = lid >> 2;
    const int cc = (lid & 3) * 2;
    if (Yf) {
#pragma unroll
        for (int mb = 0; mb < 2; mb++) {
            const int row = m0 + wm * 32 + mb * 16 + rr;
#pragma unroll
            for (int nb = 0; nb < 8; nb++) {
                const int col = n0 + wn * 64 + nb * 8 + cc;
                *(float2*)&Yf[(size_t)row * 1024 + col]       = make_float2(acc[mb][nb][0], acc[mb][nb][1]);
                *(float2*)&Yf[(size_t)(row + 8) * 1024 + col] = make_float2(acc[mb][nb][2], acc[mb][nb][3]);
            }
        }
    } else {
#pragma unroll
        for (int mb = 0; mb < 2; mb++) {
            const int row = m0 + wm * 32 + mb * 16 + rr;
#pragma unroll
            for (int nb = 0; nb < 8; nb++) {
                const int col = n0 + wn * 64 + nb * 8 + cc;
#pragma unroll
                for (int half = 0; half < 2; half++) {
                    float v0 = acc[mb][nb][half * 2 + 0] * osc;
                    float v1 = acc[mb][nb][half * 2 + 1] * osc;
                    bf16 h0 = __float2bfloat16(v0), h1 = __float2bfloat16(v1);
                    float l0 = v0 - __bfloat162float(h0), l1 = v1 - __bfloat162float(h1);
                    size_t off = (size_t)(row + half * 8) * 1024 + col;
                    *(uint32_t*)&Yh[off] = pack_bf16(__bfloat162float(h0), __bfloat162float(h1));
                    *(uint32_t*)&Yl[off] = pack_bf16(l0, l1);
                }
            }
        }
    }
}

// ---------------------------------------------------------------------------
// Flash attention, mma.sync bf16x3 — byte-exact R10-passing version
// (Q staged in smem, 110.6 KB, 1 CTA/SM).
// ---------------------------------------------------------------------------
#define AT_STR   144
#define AT_TILE  (64 * AT_STR)
#define AT_STAGE (4 * AT_TILE)
#define AT_QOFF  (2 * AT_STAGE)
#define AT_SMEM  (AT_QOFF + 2 * 128 * AT_STR)   // 110592

__global__ __launch_bounds__(256)
void attn_tc_kernel(const bf16* __restrict__ Qh, const bf16* __restrict__ Ql,
                    const bf16* __restrict__ Kh, const bf16* __restrict__ Kl,
                    const bf16* __restrict__ Vh, const bf16* __restrict__ Vl,
                    bf16* __restrict__ Ch, bf16* __restrict__ Cl)
{
    extern __shared__ char smem[];
    const uint32_t sb = smem_to_u32(smem);
    const int tid = threadIdx.x;
    const int wid = tid >> 5;
    const int lid = tid & 31;
    const int q0  = blockIdx.x * 128;
    const int h   = blockIdx.y;
    const int b   = blockIdx.z;
    const size_t ebase = ((size_t)b * S_) * D_ + (size_t)h * DK_;

    {
#pragma unroll
        for (int l = 0; l < 4; l++) {
            int idx = tid + l * 256;
            int row = idx >> 3, c8 = idx & 7;
            size_t g = ebase + (size_t)(q0 + row) * 1024 + c8 * 8;
            uint32_t s = sb + AT_QOFF + (uint32_t)row * AT_STR + c8 * 16;
            CP_ASYNC16(s, Qh + g);
            CP_ASYNC16(s + 128 * AT_STR, Ql + g);
        }
#pragma unroll
        for (int l = 0; l < 2; l++) {
            int idx = tid + l * 256;
            int row = idx >> 3, c8 = idx & 7;
            size_t g = ebase + (size_t)row * 1024 + c8 * 8;
            uint32_t s = sb + (uint32_t)row * AT_STR + c8 * 16;
            CP_ASYNC16(s + 0 * AT_TILE, Kh + g);
            CP_ASYNC16(s + 1 * AT_TILE, Kl + g);
            CP_ASYNC16(s + 2 * AT_TILE, Vh + g);
            CP_ASYNC16(s + 3 * AT_TILE, Vl + g);
        }
        CP_COMMIT();
        CP_WAIT0();
        __syncthreads();
    }

    const uint32_t qAddrBase = sb + AT_QOFF + (uint32_t)(wid * 16 + (lid & 15)) * AT_STR
                               + ((lid & 16) ? 16u : 0u);
    uint32_t qh[4][4];
#pragma unroll
    for (int ks = 0; ks < 4; ks++) ldsm4(qh[ks], qAddrBase + ks * 32);

    float m0 = -INFINITY, m1 = -INFINITY, l0 = 0.f, l1 = 0.f;
    float o[8][4];
#pragma unroll
    for (int dt = 0; dt < 8; dt++)
#pragma unroll
        for (int q = 0; q < 4; q++) o[dt][q] = 0.f;

    const uint32_t kRow = (uint32_t)((lid & 7) + ((lid & 16) ? 8 : 0)) * AT_STR + ((lid & 8) ? 16u : 0u);
    const uint32_t vRow = (uint32_t)(lid & 15) * AT_STR + ((lid & 16) ? 16u : 0u);

    for (int c = 0; c < 32; c++) {
        const uint32_t st = sb + (uint32_t)(c & 1) * AT_STAGE;

        if (c + 1 < 32) {
            const uint32_t sn = sb + (uint32_t)((c + 1) & 1) * AT_STAGE;
            const int ks0 = (c + 1) * 64;
#pragma unroll
            for (int l = 0; l < 2; l++) {
                int idx = tid + l * 256;
                int row = idx >> 3, c8 = idx & 7;
                size_t g = ebase + (size_t)(ks0 + row) * 1024 + c8 * 8;
                uint32_t s = sn + (uint32_t)row * AT_STR + c8 * 16;
                CP_ASYNC16(s + 0 * AT_TILE, Kh + g);
                CP_ASYNC16(s + 1 * AT_TILE, Kl + g);
                CP_ASYNC16(s + 2 * AT_TILE, Vh + g);
                CP_ASYNC16(s + 3 * AT_TILE, Vl + g);
            }
            CP_COMMIT();
        }

        float s4[8][4];
#pragma unroll
        for (int nt = 0; nt < 8; nt++)
#pragma unroll
            for (int q = 0; q < 4; q++) s4[nt][q] = 0.f;

#pragma unroll
        for (int ks = 0; ks < 4; ks++) {
            uint32_t bh[4][4], bl[4][4], qlr[4];
#pragma unroll
            for (int g = 0; g < 4; g++) {
                uint32_t a = st + (uint32_t)(16 * g) * AT_STR + kRow + ks * 32;
                ldsm4(bh[g], a);
                ldsm4(bl[g], a + AT_TILE);
            }
            ldsm4(qlr, qAddrBase + 128 * AT_STR + ks * 32);
#pragma unroll
            for (int nt = 0; nt < 8; nt++)
                mma_bf16(s4[nt], qh[ks], &bh[nt >> 1][(nt & 1) * 2]);
#pragma unroll
            for (int nt = 0; nt < 8; nt++)
                mma_bf16(s4[nt], qh[ks], &bl[nt >> 1][(nt & 1) * 2]);
#pragma unroll
            for (int nt = 0; nt < 8; nt++)
                mma_bf16(s4[nt], qlr,    &bh[nt >> 1][(nt & 1) * 2]);
        }

        float mx0 = -INFINITY, mx1 = -INFINITY;
#pragma unroll
        for (int nt = 0; nt < 8; nt++) {
            mx0 = fmaxf(mx0, fmaxf(s4[nt][0], s4[nt][1]));
            mx1 = fmaxf(mx1, fmaxf(s4[nt][2], s4[nt][3]));
        }
        mx0 = fmaxf(mx0, __shfl_xor_sync(0xffffffffu, mx0, 1));
        mx0 = fmaxf(mx0, __shfl_xor_sync(0xffffffffu, mx0, 2));
        mx1 = fmaxf(mx1, __shfl_xor_sync(0xffffffffu, mx1, 1));
        mx1 = fmaxf(mx1, __shfl_xor_sync(0xffffffffu, mx1, 2));
        const float mn0 = fmaxf(m0, mx0), mn1 = fmaxf(m1, mx1);
        const float f0 = __expf(m0 - mn0), f1 = __expf(m1 - mn1);
        m0 = mn0; m1 = mn1;
        float sum0 = 0.f, sum1 = 0.f;
#pragma unroll
        for (int nt = 0; nt < 8; nt++) {
            s4[nt][0] = __expf(s4[nt][0] - mn0);
            s4[nt][1] = __expf(s4[nt][1] - mn0);
            s4[nt][2] = __expf(s4[nt][2] - mn1);
            s4[nt][3] = __expf(s4[nt][3] - mn1);
            sum0 += s4[nt][0] + s4[nt][1];
            sum1 += s4[nt][2] + s4[nt][3];
        }
        sum0 += __shfl_xor_sync(0xffffffffu, sum0, 1);
        sum0 += __shfl_xor_sync(0xffffffffu, sum0, 2);
        sum1 += __shfl_xor_sync(0xffffffffu, sum1, 1);
        sum1 += __shfl_xor_sync(0xffffffffu, sum1, 2);
        l0 = l0 * f0 + sum0;
        l1 = l1 * f1 + sum1;
#pragma unroll
        for (int dt = 0; dt < 8; dt++) {
            o[dt][0] *= f0; o[dt][1] *= f0; o[dt][2] *= f1; o[dt][3] *= f1;
        }

        uint32_t ph[8][2], pl[8][2];
#pragma unroll
        for (int nt = 0; nt < 8; nt++) {
            bf16 h0 = __float2bfloat16(s4[nt][0]), h1 = __float2bfloat16(s4[nt][1]);
            bf16 h2 = __float2bfloat16(s4[nt][2]), h3 = __float2bfloat16(s4[nt][3]);
            ph[nt][0] = pack_bf16(__bfloat162float(h0), __bfloat162float(h1));
            ph[nt][1] = pack_bf16(__bfloat162float(h2), __bfloat162float(h3));
            pl[nt][0] = pack_bf16(s4[nt][0] - __bfloat162float(h0), s4[nt][1] - __bfloat162float(h1));
            pl[nt][1] = pack_bf16(s4[nt][2] - __bfloat162float(h2), s4[nt][3] - __bfloat162float(h3));
        }

#pragma unroll
        for (int ks = 0; ks < 4; ks++) {
            uint32_t pa_h[4] = { ph[2 * ks][0], ph[2 * ks][1], ph[2 * ks + 1][0], ph[2 * ks + 1][1] };
            uint32_t pa_l[4] = { pl[2 * ks][0], pl[2 * ks][1], pl[2 * ks + 1][0], pl[2 * ks + 1][1] };
#pragma unroll
            for (int dp = 0; dp < 4; dp++) {
                uint32_t vh4[4], vl4[4];
                uint32_t a = st + 2 * AT_TILE + (uint32_t)(16 * ks) * AT_STR + vRow + dp * 32;
                ldsm4t(vh4, a);
                ldsm4t(vl4, a + AT_TILE);
                mma_bf16(o[2 * dp],     pa_h, &vh4[0]);
                mma_bf16(o[2 * dp + 1], pa_h, &vh4[2]);
                mma_bf16(o[2 * dp],     pa_h, &vl4[0]);
                mma_bf16(o[2 * dp + 1], pa_h, &vl4[2]);
                mma_bf16(o[2 * dp],     pa_l, &vh4[0]);
                mma_bf16(o[2 * dp + 1], pa_l, &vh4[2]);
            }
        }

        if (c + 1 < 32) CP_WAIT0();
        __syncthreads();
    }

    const float inv0 = 1.f / l0, inv1 = 1.f / l1;
    const int r0 = q0 + wid * 16 + (lid >> 2);
    const int cc = (lid & 3) * 2;
#pragma unroll
    for (int dt = 0; dt < 8; dt++) {
        float v0 = o[dt][0] * inv0, v1 = o[dt][1] * inv0;
        float v2 = o[dt][2] * inv1, v3 = o[dt][3] * inv1;
        bf16 h0 = __float2bfloat16(v0), h1 = __float2bfloat16(v1);
        bf16 h2 = __float2bfloat16(v2), h3 = __float2bfloat16(v3);
        size_t off0 = ebase + (size_t)r0 * 1024 + dt * 8 + cc;
        size_t off1 = ebase + (size_t)(r0 + 8) * 1024 + dt * 8 + cc;
        *(uint32_t*)&Ch[off0] = pack_bf16(__bfloat162float(h0), __bfloat162float(h1));
        *(uint32_t*)&Cl[off0] = pack_bf16(v0 - __bfloat162float(h0), v1 - __bfloat162float(h1));
        *(uint32_t*)&Ch[off1] = pack_bf16(__bfloat162float(h2), __bfloat162float(h3));
        *(uint32_t*)&Cl[off1] = pack_bf16(v2 - __bfloat162float(h2), v3 - __bfloat162float(h3));
    }
}

// ---------------------------------------------------------------------------
extern "C" void kernel_launch(void* const* d_in, const int* in_sizes, int n_in,
                              void* d_out, int out_size)
{
    const float* X  = (const float*)d_in[0];
    const float* Wq = (const float*)d_in[1];
    const float* Wk = (const float*)d_in[2];
    const float* Wv = (const float*)d_in[3];
    const float* Wo = (const float*)d_in[4];
    float* out = (float*)d_out;

    bf16 *Ah, *Al, *Wh, *Wl, *Qh, *Ql, *Kh, *Kl, *Vh, *Vl;
    cudaGetSymbolAddress((void**)&Ah, g_Ah);
    cudaGetSymbolAddress((void**)&Al, g_Al);
    cudaGetSymbolAddress((void**)&Wh, g_Wh);
    cudaGetSymbolAddress((void**)&Wl, g_Wl);
    cudaGetSymbolAddress((void**)&Qh, g_Qh);
    cudaGetSymbolAddress((void**)&Ql, g_Ql);
    cudaGetSymbolAddress((void**)&Kh, g_Kh);
    cudaGetSymbolAddress((void**)&Kl, g_Kl);
    cudaGetSymbolAddress((void**)&Vh, g_Vh);
    cudaGetSymbolAddress((void**)&Vl, g_Vl);

    cudaFuncSetAttribute(gemm_tc_kernel, cudaFuncAttributeMaxDynamicSharedMemorySize, GEMM_SMEM);
    cudaFuncSetAttribute(attn_tc_kernel, cudaFuncAttributeMaxDynamicSharedMemorySize, AT_SMEM);

    const int totalBlocks = (NX_ + 4 * NW_) / 256;
    cvt_all<<<totalBlocks, 256>>>(X, Wq, Wk, Wv, Wo, Ah, Al, Wh, Wl);

    dim3 gqkv(1024 / 128, MTOT / 128, 3);
    gemm_tc_kernel<<<gqkv, 256, GEMM_SMEM>>>(
        Ah, Al,
        Wh + 0 * (size_t)NW_, Wl + 0 * (size_t)NW_,
        Wh + 1 * (size_t)NW_, Wl + 1 * (size_t)NW_,
        Wh + 2 * (size_t)NW_, Wl + 2 * (size_t)NW_,
        Qh, Ql, Kh, Kl, Vh, Vl,
        nullptr, 0.125f);

    dim3 gattn(S_ / 128, H_, B_);
    attn_tc_kernel<<<gattn, 256, AT_SMEM>>>(Qh, Ql, Kh, Kl, Vh, Vl, Ah, Al);

    dim3 go(1024 / 128, MTOT / 128, 1);
    gemm_tc_kernel<<<go, 256, GEMM_SMEM>>>(
        Ah, Al,
        Wh + 3 * (size_t)NW_, Wl + 3 * (size_t)NW_,
        Wh + 3 * (size_t)NW_, Wl + 3 * (size_t)NW_,
        Wh + 3 * (size_t)NW_, Wl + 3 * (size_t)NW_,
        Qh, Ql, Qh, Ql, Qh, Ql,
        out, 1.f);
}